// round 8
// baseline (speedup 1.0000x reference)
#include <cuda_runtime.h>
#include <math.h>
#include <stdint.h>

#define D 512
#define NMAX 20000
#define EMAX 320000

// ---------------- scratch (device globals: allocation-free) ----------------
__device__ float g_t[NMAX * D];      // tangent vectors, tf32-rounded
__device__ float g_q[NMAX * D];      // q ; later reused as h
__device__ float g_k[NMAX * D];
__device__ float g_v[NMAX * D];
__device__ float g_attn[NMAX * D];   // tf32-rounded at write
__device__ float g_Wc[4 * D * D];    // tf32-rounded weight copies (q,k,v,o)
__device__ float g_scores[EMAX];
__device__ int   g_cnt[NMAX];
__device__ int   g_off[NMAX + 1];
__device__ int   g_cur[NMAX];
__device__ int   g_srcs[EMAX];       // src node id in CSR order

__device__ __forceinline__ float f2tf32(float x) {
    uint32_t u;
    asm("cvt.rna.tf32.f32 %0, %1;" : "=r"(u) : "f"(x));
    return __uint_as_float(u);
}

__device__ __forceinline__ void cp_async16(void* sptr, const void* gptr, bool pred) {
    uint32_t sa = (uint32_t)__cvta_generic_to_shared(sptr);
    int sz = pred ? 16 : 0;
    asm volatile("cp.async.cg.shared.global [%0], [%1], 16, %2;\n"
                 :: "r"(sa), "l"(gptr), "r"(sz));
}

// ---------------- W conversion (tf32 round, once per call) -----------------
__global__ void convw_kernel(const float* __restrict__ Wq, const float* __restrict__ Wk,
                             const float* __restrict__ Wv, const float* __restrict__ Wo) {
    int i = blockIdx.x * blockDim.x + threadIdx.x;   // float4 index
    int total = 4 * D * D / 4;
    if (i >= total) return;
    int which = i / (D * D / 4);
    int off = i - which * (D * D / 4);
    const float* src = (which == 0) ? Wq : (which == 1) ? Wk : (which == 2) ? Wv : Wo;
    float4 v = ((const float4*)src)[off];
    v.x = f2tf32(v.x); v.y = f2tf32(v.y); v.z = f2tf32(v.z); v.w = f2tf32(v.w);
    ((float4*)g_Wc)[i] = v;
}

// ---------------- logmap0 (writes tf32-rounded tangent) --------------------
__global__ void logmap_kernel(const float* __restrict__ x, int n) {
    int row = blockIdx.x;
    if (row >= n) return;
    const float4* xr = (const float4*)(x + (size_t)row * D);
    float4 xv = xr[threadIdx.x];
    float ss = xv.x * xv.x + xv.y * xv.y + xv.z * xv.z + xv.w * xv.w;
    for (int o = 16; o > 0; o >>= 1) ss += __shfl_down_sync(0xffffffffu, ss, o);
    __shared__ float sred[4];
    int lane = threadIdx.x & 31, w = threadIdx.x >> 5;
    if (lane == 0) sred[w] = ss;
    __syncthreads();
    float tot = sred[0] + sred[1] + sred[2] + sred[3];
    float nrm = sqrtf(tot);
    float nc = fminf(fmaxf(nrm, 1e-7f), 1.f - 1e-6f);
    float fac = atanhf(nc) / nc;
    float4 o4;
    o4.x = f2tf32(fac * xv.x); o4.y = f2tf32(fac * xv.y);
    o4.z = f2tf32(fac * xv.z); o4.w = f2tf32(fac * xv.w);
    ((float4*)(g_t + (size_t)row * D))[threadIdx.x] = o4;
}

// ---------------- expmap0 (reads g_q as h, writes output) ------------------
__global__ void expmap_kernel(float* __restrict__ out, int n) {
    int row = blockIdx.x;
    if (row >= n) return;
    const float4* hr = (const float4*)(g_q + (size_t)row * D);
    float4 hv = hr[threadIdx.x];
    float ss = hv.x * hv.x + hv.y * hv.y + hv.z * hv.z + hv.w * hv.w;
    for (int o = 16; o > 0; o >>= 1) ss += __shfl_down_sync(0xffffffffu, ss, o);
    __shared__ float sred[4];
    int lane = threadIdx.x & 31, w = threadIdx.x >> 5;
    if (lane == 0) sred[w] = ss;
    __syncthreads();
    float tot = sred[0] + sred[1] + sred[2] + sred[3];
    float nrm = sqrtf(tot);
    float nc = fmaxf(nrm, 1e-7f);
    float fac = tanhf(nc) / nc;
    float4 o4;
    o4.x = fac * hv.x; o4.y = fac * hv.y; o4.z = fac * hv.z; o4.w = fac * hv.w;
    ((float4*)(out + (size_t)row * D))[threadIdx.x] = o4;
}

// ---------------- TF32 tensor-core GEMM (3-stage, 1 barrier/iter) ----------
//   C[M,512] = (A[M,512] @ W[512,512]^T + bias) * scale
// mode 0 (QKV): grid.x = 12, sel = bx>>2 (0/1/2), bn = (bx&3)*128, A = g_t
// mode 1 (O):   grid.x = 4,  sel = 3, bn = bx*128, A = g_attn, C = g_q
#define SM_STRIDE 36
#define TILE_FLOATS (128 * SM_STRIDE)
#define NSTAGE 3
#define GEMM_SMEM (NSTAGE * 2 * TILE_FLOATS * 4)

__global__ __launch_bounds__(256, 2)
void tgemm_kernel(const float* __restrict__ b0, const float* __restrict__ b1,
                  const float* __restrict__ b2, int mode, int M, float qscale) {
    extern __shared__ float smem[];
    int sel, bn;
    if (mode == 0) { sel = blockIdx.x >> 2; bn = (blockIdx.x & 3) << 7; }
    else           { sel = 3;               bn = blockIdx.x << 7; }
    const float* __restrict__ A = (sel == 3) ? g_attn : g_t;
    const float* __restrict__ W = g_Wc + (size_t)sel * D * D;
    float* __restrict__ C = (sel == 1) ? g_k : (sel == 2) ? g_v : g_q;
    const float* __restrict__ bias = (sel == 1) ? b1 : (sel == 2) ? b2 : b0;
    float scale = (sel == 0) ? qscale : 1.f;

    int bm = blockIdx.y * 128;
    int tid = threadIdx.x;
    int lane = tid & 31, warp = tid >> 5;
    int wm = (warp >> 2) * 64;
    int wn = (warp & 3) * 32;
    int g = lane >> 2, tg = lane & 3;
    int lrow = tid >> 3, lcol = (tid & 7) << 2;

    float acc[4][4][4];
#pragma unroll
    for (int mt = 0; mt < 4; mt++)
#pragma unroll
        for (int nt = 0; nt < 4; nt++)
#pragma unroll
            for (int i = 0; i < 4; i++) acc[mt][nt][i] = 0.f;

    auto prefetch = [&](int it) {
        float* As = smem + (it % NSTAGE) * 2 * TILE_FLOATS;
        float* Ws = As + TILE_FLOATS;
        int k0 = it * 32;
#pragma unroll
        for (int i = 0; i < 4; i++) {
            int row = lrow + i * 32;
            int ga = bm + row;
            cp_async16(&As[row * SM_STRIDE + lcol],
                       A + (size_t)ga * D + k0 + lcol, ga < M);
            cp_async16(&Ws[row * SM_STRIDE + lcol],
                       W + (size_t)(bn + row) * D + k0 + lcol, true);
        }
        asm volatile("cp.async.commit_group;\n" ::);
    };

    prefetch(0);
    prefetch(1);

    for (int it = 0; it < 16; it++) {
        // In flight at wait: {it, it+1} -> wait 1 pending == tile `it` landed.
        if (it < 15) {
            asm volatile("cp.async.wait_group 1;\n" ::);
        } else {
            asm volatile("cp.async.wait_group 0;\n" ::);
        }
        __syncthreads();   // data visible to all; compute(it-1) by all warps done
        // prefetch(it+2) targets buf (it+2)%3 == (it-1)%3, last read in
        // iteration it-1, which the barrier above just fenced.
        if (it + 2 < 16) prefetch(it + 2);

        const float* As = smem + (it % NSTAGE) * 2 * TILE_FLOATS;
        const float* Ws = As + TILE_FLOATS;

#pragma unroll
        for (int ks = 0; ks < 4; ks++) {
            int kb = ks * 8;
            uint32_t af[4][4], bf[4][2];
#pragma unroll
            for (int mt = 0; mt < 4; mt++) {
                int r = wm + mt * 16 + g;
                af[mt][0] = __float_as_uint(As[r * SM_STRIDE + kb + tg]);
                af[mt][1] = __float_as_uint(As[(r + 8) * SM_STRIDE + kb + tg]);
                af[mt][2] = __float_as_uint(As[r * SM_STRIDE + kb + tg + 4]);
                af[mt][3] = __float_as_uint(As[(r + 8) * SM_STRIDE + kb + tg + 4]);
            }
#pragma unroll
            for (int nt = 0; nt < 4; nt++) {
                int r = wn + nt * 8 + g;
                bf[nt][0] = __float_as_uint(Ws[r * SM_STRIDE + kb + tg]);
                bf[nt][1] = __float_as_uint(Ws[r * SM_STRIDE + kb + tg + 4]);
            }
#pragma unroll
            for (int mt = 0; mt < 4; mt++)
#pragma unroll
                for (int nt = 0; nt < 4; nt++) {
                    asm volatile(
                        "mma.sync.aligned.m16n8k8.row.col.f32.tf32.tf32.f32 "
                        "{%0,%1,%2,%3}, {%4,%5,%6,%7}, {%8,%9}, {%0,%1,%2,%3};"
                        : "+f"(acc[mt][nt][0]), "+f"(acc[mt][nt][1]),
                          "+f"(acc[mt][nt][2]), "+f"(acc[mt][nt][3])
                        : "r"(af[mt][0]), "r"(af[mt][1]),
                          "r"(af[mt][2]), "r"(af[mt][3]),
                          "r"(bf[nt][0]), "r"(bf[nt][1]));
                }
        }
    }

#pragma unroll
    for (int mt = 0; mt < 4; mt++) {
        int row0 = bm + wm + mt * 16 + g;
#pragma unroll
        for (int nt = 0; nt < 4; nt++) {
            int col = bn + wn + nt * 8 + tg * 2;
            float b0v = bias[col], b1v = bias[col + 1];
            if (row0 < M) {
                float2 o;
                o.x = (acc[mt][nt][0] + b0v) * scale;
                o.y = (acc[mt][nt][1] + b1v) * scale;
                *(float2*)(C + (size_t)row0 * D + col) = o;
            }
            if (row0 + 8 < M) {
                float2 o;
                o.x = (acc[mt][nt][2] + b0v) * scale;
                o.y = (acc[mt][nt][3] + b1v) * scale;
                *(float2*)(C + (size_t)(row0 + 8) * D + col) = o;
            }
        }
    }
}

// ---------------- CSR build (by dst) ----------------
__global__ void zero_cnt_kernel(int n) {
    int i = blockIdx.x * blockDim.x + threadIdx.x;
    if (i < n) g_cnt[i] = 0;
}
__global__ void hist_kernel(const int* __restrict__ dst, int E) {
    int i = blockIdx.x * blockDim.x + threadIdx.x;
    if (i < E) atomicAdd(&g_cnt[dst[i]], 1);
}
__global__ void scan_kernel(int n) {
    __shared__ int sdata[1024];
    __shared__ int carry_s;
    int t = threadIdx.x;
    if (t == 0) carry_s = 0;
    __syncthreads();
    for (int base = 0; base < n; base += 1024) {
        int idx = base + t;
        int v = (idx < n) ? g_cnt[idx] : 0;
        sdata[t] = v;
        __syncthreads();
        for (int off = 1; off < 1024; off <<= 1) {
            int tmp = (t >= off) ? sdata[t - off] : 0;
            __syncthreads();
            sdata[t] += tmp;
            __syncthreads();
        }
        int incl = sdata[t];
        int carry = carry_s;
        if (idx < n) {
            int excl = carry + incl - v;
            g_off[idx] = excl;
            g_cur[idx] = excl;
        }
        __syncthreads();
        if (t == 1023) carry_s = carry + incl;
        __syncthreads();
    }
    if (t == 0) g_off[n] = carry_s;
}
__global__ void scatter_kernel(const int* __restrict__ src,
                               const int* __restrict__ dst, int E) {
    int i = blockIdx.x * blockDim.x + threadIdx.x;
    if (i < E) {
        int p = atomicAdd(&g_cur[dst[i]], 1);
        g_srcs[p] = src[i];
    }
}

// ---------------- fused per-dst attention (256 threads) --------------------
__global__ void attn_kernel(int n) {
    int dnode = blockIdx.x;
    if (dnode >= n) return;
    int beg = g_off[dnode], end = g_off[dnode + 1];
    __shared__ float4 qs[D / 4];
    __shared__ float sred[8];
    __shared__ float s_m, s_inv;
    __shared__ int   s_src[128];
    __shared__ float s_al[128];
    int tid = threadIdx.x, lane = tid & 31, w = tid >> 5;

    if (tid < D / 4)
        qs[tid] = ((const float4*)(g_q + (size_t)dnode * D))[tid];
    __syncthreads();

    // pass 1: scores + block max (8 warps, warp per edge, float4 dots)
    float wmax = -3.4e38f;
    for (int e = beg + w; e < end; e += 8) {
        int s = g_srcs[e];
        const float4* kr = (const float4*)(g_k + (size_t)s * D);
        float acc = 0.f;
#pragma unroll
        for (int i = 0; i < 4; i++) {
            float4 kv = kr[lane + 32 * i];
            float4 qv = qs[lane + 32 * i];
            acc += kv.x * qv.x + kv.y * qv.y + kv.z * qv.z + kv.w * qv.w;
        }
        for (int o = 16; o > 0; o >>= 1) acc += __shfl_down_sync(0xffffffffu, acc, o);
        if (lane == 0) {
            g_scores[e] = acc;
            wmax = fmaxf(wmax, acc);
        }
    }
    if (lane == 0) sred[w] = wmax;
    __syncthreads();
    if (tid == 0) {
        float m0 = sred[0];
#pragma unroll
        for (int i = 1; i < 8; i++) m0 = fmaxf(m0, sred[i]);
        s_m = m0;
    }
    __syncthreads();
    float m = s_m;

    // pass 2: exp + denom
    float ds = 0.f;
    for (int e = beg + tid; e < end; e += 256) {
        float ex = expf(g_scores[e] - m);
        g_scores[e] = ex;
        ds += ex;
    }
    for (int o = 16; o > 0; o >>= 1) ds += __shfl_down_sync(0xffffffffu, ds, o);
    __syncthreads();
    if (lane == 0) sred[w] = ds;
    __syncthreads();
    if (tid == 0) {
        float t0 = 0.f;
#pragma unroll
        for (int i = 0; i < 8; i++) t0 += sred[i];
        s_inv = 1.f / t0;
    }
    __syncthreads();
    float inv = s_inv;

    // pass 3: thread owns 2 cols (float2); chunked smem staging of (src, a)
    float2 a = make_float2(0.f, 0.f);
    for (int c0 = beg; c0 < end; c0 += 128) {
        int cnt = min(128, end - c0);
        if (tid < cnt) {
            s_src[tid] = g_srcs[c0 + tid];
            s_al[tid] = g_scores[c0 + tid] * inv;
        }
        __syncthreads();
#pragma unroll 4
        for (int j = 0; j < cnt; j++) {
            int s = s_src[j];
            float al = s_al[j];
            float2 v2 = ((const float2*)(g_v + (size_t)s * D))[tid];
            a.x += al * v2.x; a.y += al * v2.y;
        }
        __syncthreads();
    }
    float2 o2;
    o2.x = f2tf32(a.x); o2.y = f2tf32(a.y);
    ((float2*)(g_attn + (size_t)dnode * D))[tid] = o2;
}

// ---------------- launch ----------------
extern "C" void kernel_launch(void* const* d_in, const int* in_sizes, int n_in,
                              void* d_out, int out_size) {
    const float* x  = (const float*)d_in[0];
    const int*   src = (const int*)d_in[1];
    const int*   dst = (const int*)d_in[2];
    const float* Wq = (const float*)d_in[3];
    const float* bq = (const float*)d_in[4];
    const float* Wk = (const float*)d_in[5];
    const float* bk = (const float*)d_in[6];
    const float* Wv = (const float*)d_in[7];
    const float* bv = (const float*)d_in[8];
    const float* Wo = (const float*)d_in[9];
    const float* bo = (const float*)d_in[10];
    float* out = (float*)d_out;

    int n = in_sizes[0] / D;
    int E = in_sizes[1];
    float qscale = 1.f / sqrtf((float)D);

    static cudaStream_t s2 = nullptr;
    static cudaEvent_t evFork = nullptr, evW = nullptr, evJoin = nullptr;
    if (!s2) {
        cudaStreamCreateWithFlags(&s2, cudaStreamNonBlocking);
        cudaEventCreateWithFlags(&evFork, cudaEventDisableTiming);
        cudaEventCreateWithFlags(&evW, cudaEventDisableTiming);
        cudaEventCreateWithFlags(&evJoin, cudaEventDisableTiming);
    }

    cudaFuncSetAttribute(tgemm_kernel,
                         cudaFuncAttributeMaxDynamicSharedMemorySize, GEMM_SMEM);

    cudaEventRecord(evFork, 0);
    cudaStreamWaitEvent(s2, evFork, 0);

    convw_kernel<<<(4 * D * D / 4 + 255) / 256, 256, 0, s2>>>(Wq, Wk, Wv, Wo);
    cudaEventRecord(evW, s2);
    zero_cnt_kernel<<<(n + 255) / 256, 256, 0, s2>>>(n);
    hist_kernel<<<(E + 255) / 256, 256, 0, s2>>>(dst, E);
    scan_kernel<<<1, 1024, 0, s2>>>(n);
    scatter_kernel<<<(E + 255) / 256, 256, 0, s2>>>(src, dst, E);
    cudaEventRecord(evJoin, s2);

    logmap_kernel<<<n, 128>>>(x, n);
    cudaStreamWaitEvent(0, evW, 0);

    dim3 gqkv(12, (n + 127) / 128);
    tgemm_kernel<<<gqkv, 256, GEMM_SMEM>>>(bq, bk, bv, 0, n, qscale);

    cudaStreamWaitEvent(0, evJoin, 0);
    attn_kernel<<<n, 256>>>(n);

    dim3 go(4, (n + 127) / 128);
    tgemm_kernel<<<go, 256, GEMM_SMEM>>>(bo, bo, bo, 1, n, 1.f);
    expmap_kernel<<<n, 128>>>(out, n);
}

// round 9
// speedup vs baseline: 1.1104x; 1.1104x over previous
#include <cuda_runtime.h>
#include <math.h>
#include <stdint.h>

#define D 512
#define NMAX 20000
#define EMAX 320000

// ---------------- scratch (device globals: allocation-free) ----------------
__device__ float g_t[NMAX * D];      // tangent vectors, tf32-rounded
__device__ float g_q[NMAX * D];      // q ; later reused as h
__device__ float g_k[NMAX * D];
__device__ float g_v[NMAX * D];
__device__ float g_attn[NMAX * D];   // tf32-rounded at write
__device__ float g_Wc[4 * D * D];    // tf32-rounded weight copies (q,k,v,o)
__device__ float g_scores[EMAX];
__device__ int   g_cnt[NMAX];
__device__ int   g_off[NMAX + 1];
__device__ int   g_cur[NMAX];
__device__ int   g_srcs[EMAX];       // src node id in CSR order

__device__ __forceinline__ float f2tf32(float x) {
    uint32_t u;
    asm("cvt.rna.tf32.f32 %0, %1;" : "=r"(u) : "f"(x));
    return __uint_as_float(u);
}

__device__ __forceinline__ void cp_async16(void* sptr, const void* gptr, bool pred) {
    uint32_t sa = (uint32_t)__cvta_generic_to_shared(sptr);
    int sz = pred ? 16 : 0;
    asm volatile("cp.async.cg.shared.global [%0], [%1], 16, %2;\n"
                 :: "r"(sa), "l"(gptr), "r"(sz));
}

// ---------------- W conversion (tf32 round, once per call) -----------------
__global__ void convw_kernel(const float* __restrict__ Wq, const float* __restrict__ Wk,
                             const float* __restrict__ Wv, const float* __restrict__ Wo) {
    int i = blockIdx.x * blockDim.x + threadIdx.x;   // float4 index
    int total = 4 * D * D / 4;
    if (i >= total) return;
    int which = i / (D * D / 4);
    int off = i - which * (D * D / 4);
    const float* src = (which == 0) ? Wq : (which == 1) ? Wk : (which == 2) ? Wv : Wo;
    float4 v = ((const float4*)src)[off];
    v.x = f2tf32(v.x); v.y = f2tf32(v.y); v.z = f2tf32(v.z); v.w = f2tf32(v.w);
    ((float4*)g_Wc)[i] = v;
}

// ---------------- logmap0 (writes tf32-rounded tangent) --------------------
__global__ void logmap_kernel(const float* __restrict__ x, int n) {
    int row = blockIdx.x;
    if (row >= n) return;
    const float4* xr = (const float4*)(x + (size_t)row * D);
    float4 xv = xr[threadIdx.x];
    float ss = xv.x * xv.x + xv.y * xv.y + xv.z * xv.z + xv.w * xv.w;
    for (int o = 16; o > 0; o >>= 1) ss += __shfl_down_sync(0xffffffffu, ss, o);
    __shared__ float sred[4];
    int lane = threadIdx.x & 31, w = threadIdx.x >> 5;
    if (lane == 0) sred[w] = ss;
    __syncthreads();
    float tot = sred[0] + sred[1] + sred[2] + sred[3];
    float nrm = sqrtf(tot);
    float nc = fminf(fmaxf(nrm, 1e-7f), 1.f - 1e-6f);
    float fac = atanhf(nc) / nc;
    float4 o4;
    o4.x = f2tf32(fac * xv.x); o4.y = f2tf32(fac * xv.y);
    o4.z = f2tf32(fac * xv.z); o4.w = f2tf32(fac * xv.w);
    ((float4*)(g_t + (size_t)row * D))[threadIdx.x] = o4;
}

// ---------------- expmap0 (reads g_q as h, writes output) ------------------
__global__ void expmap_kernel(float* __restrict__ out, int n) {
    int row = blockIdx.x;
    if (row >= n) return;
    const float4* hr = (const float4*)(g_q + (size_t)row * D);
    float4 hv = hr[threadIdx.x];
    float ss = hv.x * hv.x + hv.y * hv.y + hv.z * hv.z + hv.w * hv.w;
    for (int o = 16; o > 0; o >>= 1) ss += __shfl_down_sync(0xffffffffu, ss, o);
    __shared__ float sred[4];
    int lane = threadIdx.x & 31, w = threadIdx.x >> 5;
    if (lane == 0) sred[w] = ss;
    __syncthreads();
    float tot = sred[0] + sred[1] + sred[2] + sred[3];
    float nrm = sqrtf(tot);
    float nc = fmaxf(nrm, 1e-7f);
    float fac = tanhf(nc) / nc;
    float4 o4;
    o4.x = fac * hv.x; o4.y = fac * hv.y; o4.z = fac * hv.z; o4.w = fac * hv.w;
    ((float4*)(out + (size_t)row * D))[threadIdx.x] = o4;
}

// ---------------- TF32 tensor-core GEMM (3-stage, 1 barrier/iter) ----------
//   C[M,512] = (A[M,512] @ W[512,512]^T + bias) * scale
// mode 0 (QKV): grid.x = 12, sel = bx>>2 (0/1/2), bn = (bx&3)*128, A = g_t
// mode 1 (O):   grid.x = 4,  sel = 3, bn = bx*128, A = g_attn, C = g_q
#define SM_STRIDE 36
#define TILE_FLOATS (128 * SM_STRIDE)
#define NSTAGE 3
#define GEMM_SMEM (NSTAGE * 2 * TILE_FLOATS * 4)

__global__ __launch_bounds__(256, 2)
void tgemm_kernel(const float* __restrict__ b0, const float* __restrict__ b1,
                  const float* __restrict__ b2, int mode, int M, float qscale) {
    extern __shared__ float smem[];
    int sel, bn;
    if (mode == 0) { sel = blockIdx.x >> 2; bn = (blockIdx.x & 3) << 7; }
    else           { sel = 3;               bn = blockIdx.x << 7; }
    const float* __restrict__ A = (sel == 3) ? g_attn : g_t;
    const float* __restrict__ W = g_Wc + (size_t)sel * D * D;
    float* __restrict__ C = (sel == 1) ? g_k : (sel == 2) ? g_v : g_q;
    const float* __restrict__ bias = (sel == 1) ? b1 : (sel == 2) ? b2 : b0;
    float scale = (sel == 0) ? qscale : 1.f;

    int bm = blockIdx.y * 128;
    int tid = threadIdx.x;
    int lane = tid & 31, warp = tid >> 5;
    int wm = (warp >> 2) * 64;
    int wn = (warp & 3) * 32;
    int g = lane >> 2, tg = lane & 3;
    int lrow = tid >> 3, lcol = (tid & 7) << 2;

    float acc[4][4][4];
#pragma unroll
    for (int mt = 0; mt < 4; mt++)
#pragma unroll
        for (int nt = 0; nt < 4; nt++)
#pragma unroll
            for (int i = 0; i < 4; i++) acc[mt][nt][i] = 0.f;

    auto prefetch = [&](int it) {
        float* As = smem + (it % NSTAGE) * 2 * TILE_FLOATS;
        float* Ws = As + TILE_FLOATS;
        int k0 = it * 32;
#pragma unroll
        for (int i = 0; i < 4; i++) {
            int row = lrow + i * 32;
            int ga = bm + row;
            cp_async16(&As[row * SM_STRIDE + lcol],
                       A + (size_t)ga * D + k0 + lcol, ga < M);
            cp_async16(&Ws[row * SM_STRIDE + lcol],
                       W + (size_t)(bn + row) * D + k0 + lcol, true);
        }
        asm volatile("cp.async.commit_group;\n" ::);
    };

    prefetch(0);
    prefetch(1);

    for (int it = 0; it < 16; it++) {
        // In flight at wait: {it, it+1} -> wait 1 pending == tile `it` landed.
        if (it < 15) {
            asm volatile("cp.async.wait_group 1;\n" ::);
        } else {
            asm volatile("cp.async.wait_group 0;\n" ::);
        }
        __syncthreads();   // all warps done with compute(it-1)
        // prefetch(it+2) targets buf (it+2)%3 == (it-1)%3, last read in
        // iteration it-1, which the barrier above just fenced.
        if (it + 2 < 16) prefetch(it + 2);

        const float* As = smem + (it % NSTAGE) * 2 * TILE_FLOATS;
        const float* Ws = As + TILE_FLOATS;

#pragma unroll
        for (int ks = 0; ks < 4; ks++) {
            int kb = ks * 8;
            uint32_t af[4][4], bf[4][2];
#pragma unroll
            for (int mt = 0; mt < 4; mt++) {
                int r = wm + mt * 16 + g;
                af[mt][0] = __float_as_uint(As[r * SM_STRIDE + kb + tg]);
                af[mt][1] = __float_as_uint(As[(r + 8) * SM_STRIDE + kb + tg]);
                af[mt][2] = __float_as_uint(As[r * SM_STRIDE + kb + tg + 4]);
                af[mt][3] = __float_as_uint(As[(r + 8) * SM_STRIDE + kb + tg + 4]);
            }
#pragma unroll
            for (int nt = 0; nt < 4; nt++) {
                int r = wn + nt * 8 + g;
                bf[nt][0] = __float_as_uint(Ws[r * SM_STRIDE + kb + tg]);
                bf[nt][1] = __float_as_uint(Ws[r * SM_STRIDE + kb + tg + 4]);
            }
#pragma unroll
            for (int mt = 0; mt < 4; mt++)
#pragma unroll
                for (int nt = 0; nt < 4; nt++) {
                    asm volatile(
                        "mma.sync.aligned.m16n8k8.row.col.f32.tf32.tf32.f32 "
                        "{%0,%1,%2,%3}, {%4,%5,%6,%7}, {%8,%9}, {%0,%1,%2,%3};"
                        : "+f"(acc[mt][nt][0]), "+f"(acc[mt][nt][1]),
                          "+f"(acc[mt][nt][2]), "+f"(acc[mt][nt][3])
                        : "r"(af[mt][0]), "r"(af[mt][1]),
                          "r"(af[mt][2]), "r"(af[mt][3]),
                          "r"(bf[nt][0]), "r"(bf[nt][1]));
                }
        }
    }

#pragma unroll
    for (int mt = 0; mt < 4; mt++) {
        int row0 = bm + wm + mt * 16 + g;
#pragma unroll
        for (int nt = 0; nt < 4; nt++) {
            int col = bn + wn + nt * 8 + tg * 2;
            float b0v = bias[col], b1v = bias[col + 1];
            if (row0 < M) {
                float2 o;
                o.x = (acc[mt][nt][0] + b0v) * scale;
                o.y = (acc[mt][nt][1] + b1v) * scale;
                *(float2*)(C + (size_t)row0 * D + col) = o;
            }
            if (row0 + 8 < M) {
                float2 o;
                o.x = (acc[mt][nt][2] + b0v) * scale;
                o.y = (acc[mt][nt][3] + b1v) * scale;
                *(float2*)(C + (size_t)(row0 + 8) * D + col) = o;
            }
        }
    }
}

// ---------------- CSR build (by dst) ----------------
__global__ void zero_cnt_kernel(int n) {
    int i = blockIdx.x * blockDim.x + threadIdx.x;
    if (i < n) g_cnt[i] = 0;
}
__global__ void hist_kernel(const int* __restrict__ dst, int E) {
    int i = blockIdx.x * blockDim.x + threadIdx.x;
    if (i < E) atomicAdd(&g_cnt[dst[i]], 1);
}
__global__ void scan_kernel(int n) {
    __shared__ int sdata[1024];
    __shared__ int carry_s;
    int t = threadIdx.x;
    if (t == 0) carry_s = 0;
    __syncthreads();
    for (int base = 0; base < n; base += 1024) {
        int idx = base + t;
        int v = (idx < n) ? g_cnt[idx] : 0;
        sdata[t] = v;
        __syncthreads();
        for (int off = 1; off < 1024; off <<= 1) {
            int tmp = (t >= off) ? sdata[t - off] : 0;
            __syncthreads();
            sdata[t] += tmp;
            __syncthreads();
        }
        int incl = sdata[t];
        int carry = carry_s;
        if (idx < n) {
            int excl = carry + incl - v;
            g_off[idx] = excl;
            g_cur[idx] = excl;
        }
        __syncthreads();
        if (t == 1023) carry_s = carry + incl;
        __syncthreads();
    }
    if (t == 0) g_off[n] = carry_s;
}
__global__ void scatter_kernel(const int* __restrict__ src,
                               const int* __restrict__ dst, int E) {
    int i = blockIdx.x * blockDim.x + threadIdx.x;
    if (i < E) {
        int p = atomicAdd(&g_cur[dst[i]], 1);
        g_srcs[p] = src[i];
    }
}

// ---------------- fused per-dst attention (128 threads, R7 version) --------
__global__ void attn_kernel(int n) {
    int dnode = blockIdx.x;
    if (dnode >= n) return;
    int beg = g_off[dnode], end = g_off[dnode + 1];
    __shared__ float4 qs[D / 4];
    __shared__ float sred[4];
    __shared__ float s_m, s_inv;
    __shared__ int   s_src[128];
    __shared__ float s_al[128];
    int tid = threadIdx.x, lane = tid & 31, w = tid >> 5;

    qs[tid] = ((const float4*)(g_q + (size_t)dnode * D))[tid];
    __syncthreads();

    // pass 1: scores + block max (warp per edge, float4 dots)
    float wmax = -3.4e38f;
    for (int e = beg + w; e < end; e += 4) {
        int s = g_srcs[e];
        const float4* kr = (const float4*)(g_k + (size_t)s * D);
        float acc = 0.f;
#pragma unroll
        for (int i = 0; i < 4; i++) {
            float4 kv = kr[lane + 32 * i];
            float4 qv = qs[lane + 32 * i];
            acc += kv.x * qv.x + kv.y * qv.y + kv.z * qv.z + kv.w * qv.w;
        }
        for (int o = 16; o > 0; o >>= 1) acc += __shfl_down_sync(0xffffffffu, acc, o);
        if (lane == 0) {
            g_scores[e] = acc;
            wmax = fmaxf(wmax, acc);
        }
    }
    if (lane == 0) sred[w] = wmax;
    __syncthreads();
    if (tid == 0)
        s_m = fmaxf(fmaxf(sred[0], sred[1]), fmaxf(sred[2], sred[3]));
    __syncthreads();
    float m = s_m;

    // pass 2: exp + denom
    float ds = 0.f;
    for (int e = beg + tid; e < end; e += 128) {
        float ex = expf(g_scores[e] - m);
        g_scores[e] = ex;
        ds += ex;
    }
    for (int o = 16; o > 0; o >>= 1) ds += __shfl_down_sync(0xffffffffu, ds, o);
    __syncthreads();
    if (lane == 0) sred[w] = ds;
    __syncthreads();
    if (tid == 0) s_inv = 1.f / (sred[0] + sred[1] + sred[2] + sred[3]);
    __syncthreads();
    float inv = s_inv;

    // pass 3: chunked smem staging of (src, alpha); float4 per thread
    float4 a = make_float4(0.f, 0.f, 0.f, 0.f);
    for (int c0 = beg; c0 < end; c0 += 128) {
        int cnt = min(128, end - c0);
        if (tid < cnt) {
            s_src[tid] = g_srcs[c0 + tid];
            s_al[tid] = g_scores[c0 + tid] * inv;
        }
        __syncthreads();
#pragma unroll 4
        for (int j = 0; j < cnt; j++) {
            int s = s_src[j];
            float al = s_al[j];
            float4 v4 = ((const float4*)(g_v + (size_t)s * D))[tid];
            a.x += al * v4.x; a.y += al * v4.y;
            a.z += al * v4.z; a.w += al * v4.w;
        }
        __syncthreads();
    }
    float4 o4;
    o4.x = f2tf32(a.x); o4.y = f2tf32(a.y);
    o4.z = f2tf32(a.z); o4.w = f2tf32(a.w);
    ((float4*)(g_attn + (size_t)dnode * D))[tid] = o4;
}

// ---------------- launch ----------------
extern "C" void kernel_launch(void* const* d_in, const int* in_sizes, int n_in,
                              void* d_out, int out_size) {
    const float* x  = (const float*)d_in[0];
    const int*   src = (const int*)d_in[1];
    const int*   dst = (const int*)d_in[2];
    const float* Wq = (const float*)d_in[3];
    const float* bq = (const float*)d_in[4];
    const float* Wk = (const float*)d_in[5];
    const float* bk = (const float*)d_in[6];
    const float* Wv = (const float*)d_in[7];
    const float* bv = (const float*)d_in[8];
    const float* Wo = (const float*)d_in[9];
    const float* bo = (const float*)d_in[10];
    float* out = (float*)d_out;

    int n = in_sizes[0] / D;
    int E = in_sizes[1];
    float qscale = 1.f / sqrtf((float)D);

    static cudaStream_t s2 = nullptr;
    static cudaEvent_t evFork = nullptr, evW = nullptr, evJoin = nullptr;
    if (!s2) {
        cudaStreamCreateWithFlags(&s2, cudaStreamNonBlocking);
        cudaEventCreateWithFlags(&evFork, cudaEventDisableTiming);
        cudaEventCreateWithFlags(&evW, cudaEventDisableTiming);
        cudaEventCreateWithFlags(&evJoin, cudaEventDisableTiming);
    }

    cudaFuncSetAttribute(tgemm_kernel,
                         cudaFuncAttributeMaxDynamicSharedMemorySize, GEMM_SMEM);

    cudaEventRecord(evFork, 0);
    cudaStreamWaitEvent(s2, evFork, 0);

    convw_kernel<<<(4 * D * D / 4 + 255) / 256, 256, 0, s2>>>(Wq, Wk, Wv, Wo);
    cudaEventRecord(evW, s2);
    zero_cnt_kernel<<<(n + 255) / 256, 256, 0, s2>>>(n);
    hist_kernel<<<(E + 255) / 256, 256, 0, s2>>>(dst, E);
    scan_kernel<<<1, 1024, 0, s2>>>(n);
    scatter_kernel<<<(E + 255) / 256, 256, 0, s2>>>(src, dst, E);
    cudaEventRecord(evJoin, s2);

    logmap_kernel<<<n, 128>>>(x, n);
    cudaStreamWaitEvent(0, evW, 0);

    dim3 gqkv(12, (n + 127) / 128);
    tgemm_kernel<<<gqkv, 256, GEMM_SMEM>>>(bq, bk, bv, 0, n, qscale);

    cudaStreamWaitEvent(0, evJoin, 0);
    attn_kernel<<<n, 128>>>(n);

    dim3 go(4, (n + 127) / 128);
    tgemm_kernel<<<go, 256, GEMM_SMEM>>>(bo, bo, bo, 1, n, 1.f);
    expmap_kernel<<<n, 128>>>(out, n);
}